// round 13
// baseline (speedup 1.0000x reference)
#include <cuda_runtime.h>
#include <math.h>
#include <cstdint>

#define N_NODES 10000
#define N_EDGES 160000
#define FDIM 128
#define NRBD 32
#define PHI_DIM 1024

// scratch (static device globals: allocation-free)
__device__ float g_h[N_NODES * FDIM];        // silu(s@W1+b1)
__device__ float g_phi[N_NODES * PHI_DIM];   // phi, TRANSPOSED: [n][ff*8+c]
__device__ float g_vt[N_NODES * FDIM * 4];   // v transposed: [n][ff][4] (xyz,pad)
__device__ float g_scr[N_NODES * FDIM * 4];  // accum: [n][ff][{s,vx,vy,vz}]

// ---------------- packed f32x2 helpers (Blackwell FFMA2) ----------------
__device__ __forceinline__ unsigned long long pack2(float lo, float hi) {
    unsigned long long r;
    asm("mov.b64 %0, {%1, %2};" : "=l"(r) : "f"(lo), "f"(hi));
    return r;
}
__device__ __forceinline__ unsigned long long fma2(unsigned long long a,
                                                   unsigned long long b,
                                                   unsigned long long c) {
    unsigned long long d;
    asm("fma.rn.f32x2 %0, %1, %2, %3;" : "=l"(d) : "l"(a), "l"(b), "l"(c));
    return d;
}
__device__ __forceinline__ float2 unpack2(unsigned long long p) {
    float2 f;
    asm("mov.b64 {%0, %1}, %2;" : "=f"(f.x), "=f"(f.y) : "l"(p));
    return f;
}
__device__ __forceinline__ void red_add_v4(float* addr, float a, float b,
                                           float c, float d) {
    asm volatile("red.global.add.v4.f32 [%0], {%1, %2, %3, %4};"
                 :: "l"(addr), "f"(a), "f"(b), "f"(c), "f"(d) : "memory");
}

// ---------------- init: out = concat(s, v); build vt; zero scr ------------
__global__ void init_out_kernel(const float* __restrict__ s,
                                const float* __restrict__ v,
                                float* __restrict__ out) {
    int ns4 = (N_NODES * FDIM) / 4;
    int nv4 = (N_NODES * 3 * FDIM) / 4;
    int total4 = ns4 + nv4;
    for (int t = blockIdx.x * blockDim.x + threadIdx.x; t < total4;
         t += gridDim.x * blockDim.x) {
        float4 val = (t < ns4) ? ((const float4*)s)[t]
                               : ((const float4*)v)[t - ns4];
        ((float4*)out)[t] = val;
    }
}

__global__ void prep_kernel(const float* __restrict__ v) {
    int total = N_NODES * FDIM;
    for (int t = blockIdx.x * blockDim.x + threadIdx.x; t < total;
         t += gridDim.x * blockDim.x) {
        int n = t >> 7, ff = t & 127;
        const float* vp = v + (size_t)n * (3 * FDIM) + ff;
        float4 w;
        w.x = vp[0];
        w.y = vp[128];
        w.z = vp[256];
        w.w = 0.f;
        ((float4*)g_vt)[t] = w;
        ((float4*)g_scr)[t] = make_float4(0.f, 0.f, 0.f, 0.f);
    }
}

// ---------------- merge: out += scr (scatter back to harness layout) -------
__global__ void merge_kernel(float* __restrict__ out) {
    int total = N_NODES * FDIM;
    float* out_v = out + (size_t)N_NODES * FDIM;
    for (int t = blockIdx.x * blockDim.x + threadIdx.x; t < total;
         t += gridDim.x * blockDim.x) {
        float4 a = ((const float4*)g_scr)[t];
        int n = t >> 7, ff = t & 127;
        out[t] += a.x;
        float* ov = out_v + (size_t)n * (3 * FDIM) + ff;
        ov[0] += a.y;
        ov[128] += a.z;
        ov[256] += a.w;
    }
}

// ---------------- SGEMM: C = A[M,K] @ B[K,N] + bias --------------------
// BM=128, BN=64, BK=16, TM=8, TN=4, 256 threads, FFMA2 inner loop.
// TPOSE: write C[r][(c%128)*8 + c/128]  (phi chunk-transposed layout)
template <bool SILU, bool TPOSE>
__global__ __launch_bounds__(256) void sgemm_kernel(
    const float* __restrict__ A, const float* __restrict__ B,
    const float* __restrict__ bias, float* __restrict__ C,
    int M, int N, int K) {
    __shared__ float As[16][132];
    __shared__ float Bs[16][64];

    int tid = threadIdx.x;
    int tx = tid % 16, ty = tid / 16;
    int bRow = blockIdx.y * 128, bCol = blockIdx.x * 64;
    int bRowL = tid / 16, bColL = (tid % 16) * 4;

    unsigned long long accp[8][2];
#pragma unroll
    for (int i = 0; i < 8; i++) {
        accp[i][0] = 0ULL;
        accp[i][1] = 0ULL;
    }

    for (int kt = 0; kt < K; kt += 16) {
#pragma unroll
        for (int l = 0; l < 2; l++) {
            int idx = tid + l * 256;
            int row = idx >> 2, c4 = (idx & 3) * 4;
            float4 a = make_float4(0.f, 0.f, 0.f, 0.f);
            int gRow = bRow + row;
            if (gRow < M) a = *(const float4*)(A + (size_t)gRow * K + kt + c4);
            As[c4 + 0][row] = a.x;
            As[c4 + 1][row] = a.y;
            As[c4 + 2][row] = a.z;
            As[c4 + 3][row] = a.w;
        }
        float4 b = *(const float4*)(B + (size_t)(kt + bRowL) * N + bCol + bColL);
        *(float4*)&Bs[bRowL][bColL] = b;
        __syncthreads();

#pragma unroll
        for (int k = 0; k < 16; ++k) {
            float4 bn = *(float4*)&Bs[k][tx * 4];
            unsigned long long pb0 = pack2(bn.x, bn.y);
            unsigned long long pb1 = pack2(bn.z, bn.w);
#pragma unroll
            for (int i = 0; i < 8; i++) {
                float rm = As[k][ty * 8 + i];
                unsigned long long rd = pack2(rm, rm);
                accp[i][0] = fma2(rd, pb0, accp[i][0]);
                accp[i][1] = fma2(rd, pb1, accp[i][1]);
            }
        }
        __syncthreads();
    }

#pragma unroll
    for (int i = 0; i < 8; i++) {
        int r = bRow + ty * 8 + i;
        if (r >= M) continue;
        float2 p0 = unpack2(accp[i][0]);
        float2 p1 = unpack2(accp[i][1]);
        float vals[4] = {p0.x, p0.y, p1.x, p1.y};
#pragma unroll
        for (int j = 0; j < 4; j++) {
            int c = bCol + tx * 4 + j;
            float val = vals[j] + bias[c];
            if (SILU) val = val / (1.0f + expf(-val));
            int cc = TPOSE ? ((c & 127) * 8 + (c >> 7)) : c;
            C[(size_t)r * N + cc] = val;
        }
    }
}

// ---------------- fused edge kernel (pipelined, vectorized epilogue) -------
// 512 threads = 4 eslots x 128 features; 8 edges/eslot per 32-edge tile.
// Wr resident in SMEM; FFMA2 mainloop with native chunk-pair LDS; tile
// staging double-buffered (one barrier/tile). Epilogue per edge: 2 LDG.128
// (phi_t) + 1 LDG.128 (vt) + 1 red.global.add.v4 into scr.
__global__ __launch_bounds__(512, 1) void edge_kernel(
    const float* __restrict__ re1, const float* __restrict__ re2,
    const float* __restrict__ re3, const float* __restrict__ fc1,
    const float* __restrict__ fc2, const float* __restrict__ fc3,
    const float* __restrict__ uv1, const float* __restrict__ uv2,
    const float* __restrict__ uv3, const int* __restrict__ eidx,
    const float* __restrict__ Wr, const float* __restrict__ br) {
    extern __shared__ float smem[];
    float4* wrA = (float4*)smem;          // [32*128] chunks 0..3
    float4* wrB = wrA + NRBD * FDIM;      // [32*128] chunks 4..7
    float4* rc4 = wrB + NRBD * FDIM;      // [2][32 edges][8]
    float* uvs = (float*)(rc4 + 2 * 256); // [2][32*9]
    float* fcs = uvs + 2 * 288;           // [2][32]
    int* iis = (int*)(fcs + 2 * 32);      // [2][32]
    int* jjs = iis + 2 * 32;              // [2][32]

    int tid = threadIdx.x;

    // one-time Wr load into transposed/split SMEM layout
    for (int idx = tid; idx < NRBD * PHI_DIM; idx += 512) {
        int k = idx >> 10;
        int col = idx & 1023;
        int c = col >> 7, ffi = col & 127;
        float val = Wr[idx];
        float* dst = (c < 4) ? (float*)&wrA[k * FDIM + ffi]
                             : (float*)&wrB[k * FDIM + ffi];
        dst[c & 3] = val;
    }

    int ff = tid & 127;
    int eslot = tid >> 7;

    float brc[8];
#pragma unroll
    for (int c = 0; c < 8; c++) brc[c] = br[c * FDIM + ff];

    const int numTiles = N_EDGES / 32;

    // ---- staging lambda (writes one buffer, no sync) ----
    auto stage = [&](int buf, int tileId) {
        int eBase = tileId * 32;
        if (tid < 256) {
            int t = tid;
            int e = t >> 3;
            int ge = eBase + e;
            float c1 = fc1[ge], c2 = fc2[ge], c3 = fc3[ge];
            float4 a = ((const float4*)re1)[ge * 8 + (t & 7)];
            float4 b = ((const float4*)re2)[ge * 8 + (t & 7)];
            float4 c = ((const float4*)re3)[ge * 8 + (t & 7)];
            float4 r;
            r.x = a.x * c1 + b.x * c2 + c.x * c3;
            r.y = a.y * c1 + b.y * c2 + c.y * c3;
            r.z = a.z * c1 + b.z * c2 + c.z * c3;
            r.w = a.w * c1 + b.w * c2 + c.w * c3;
            rc4[buf * 256 + t] = r;
        } else if (tid < 288) {
            int le = tid - 256;
            int ge = eBase + le;
            iis[buf * 32 + le] = eidx[ge];
            jjs[buf * 32 + le] = eidx[N_EDGES + ge];
            fcs[buf * 32 + le] = fc1[ge] + fc2[ge] + fc3[ge];
#pragma unroll
            for (int d = 0; d < 3; d++) {
                uvs[buf * 288 + le * 9 + d] = uv1[ge * 3 + d];
                uvs[buf * 288 + le * 9 + 3 + d] = uv2[ge * 3 + d];
                uvs[buf * 288 + le * 9 + 6 + d] = uv3[ge * 3 + d];
            }
        }
    };

    // prologue: stage first tile into buffer 0
    stage(0, blockIdx.x);
    int cur = 0;

    for (int tile = blockIdx.x; tile < numTiles; tile += gridDim.x) {
        __syncthreads();  // staging of buffer `cur` complete; prev reads done

        int nxt = tile + gridDim.x;
        if (nxt < numTiles) stage(1 - cur, nxt);

        const float4* rcb = rc4 + cur * 256;
        const float* fcb = fcs + cur * 32;
        const float* uvb = uvs + cur * 288;
        const int* iib = iis + cur * 32;
        const int* jjb = jjs + cur * 32;

        // W accumulators: 8 edges x 4 chunk-pairs, packed f32x2
        unsigned long long accp[8][4];
#pragma unroll
        for (int e = 0; e < 8; e++) {
            float fs = fcb[eslot * 8 + e];
            accp[e][0] = pack2(fs * brc[0], fs * brc[1]);
            accp[e][1] = pack2(fs * brc[2], fs * brc[3]);
            accp[e][2] = pack2(fs * brc[4], fs * brc[5]);
            accp[e][3] = pack2(fs * brc[6], fs * brc[7]);
        }

#pragma unroll
        for (int kk = 0; kk < 8; ++kk) {
            float4 r[8];
#pragma unroll
            for (int e = 0; e < 8; e++) r[e] = rcb[(eslot * 8 + e) * 8 + kk];
#pragma unroll
            for (int d = 0; d < 4; ++d) {
                int k = kk * 4 + d;
                ulonglong2 wa = *(const ulonglong2*)&wrA[k * FDIM + ff];
                ulonglong2 wb = *(const ulonglong2*)&wrB[k * FDIM + ff];
#pragma unroll
                for (int e = 0; e < 8; e++) {
                    float rv = (d == 0) ? r[e].x
                             : (d == 1) ? r[e].y
                             : (d == 2) ? r[e].z
                                        : r[e].w;
                    unsigned long long rp = pack2(rv, rv);
                    accp[e][0] = fma2(rp, wa.x, accp[e][0]);
                    accp[e][1] = fma2(rp, wa.y, accp[e][1]);
                    accp[e][2] = fma2(rp, wb.x, accp[e][2]);
                    accp[e][3] = fma2(rp, wb.y, accp[e][3]);
                }
            }
        }

        // epilogue: pairs of edges; 3 LDG.128 per edge, hoisted; 1 red.v4
#pragma unroll
        for (int pp = 0; pp < 4; pp++) {
            int le0 = eslot * 8 + 2 * pp;
            int le1 = le0 + 1;
            int i0 = iib[le0], j0 = jjb[le0];
            int i1 = iib[le1], j1 = jjb[le1];

            const float4* pt0 = (const float4*)(g_phi + (size_t)j0 * PHI_DIM + ff * 8);
            const float4* pt1 = (const float4*)(g_phi + (size_t)j1 * PHI_DIM + ff * 8);
            float4 pa0 = pt0[0], pb0 = pt0[1];
            float4 pa1 = pt1[0], pb1 = pt1[1];
            float4 vv0 = ((const float4*)g_vt)[(size_t)j0 * FDIM + ff];
            float4 vv1 = ((const float4*)g_vt)[(size_t)j1 * FDIM + ff];

#pragma unroll
            for (int q = 0; q < 2; q++) {
                int le = q ? le1 : le0;
                int i = q ? i1 : i0;
                float4 pa = q ? pa1 : pa0;
                float4 pb = q ? pb1 : pb0;
                float4 vw = q ? vv1 : vv0;
                int eloc = le - eslot * 8;
                float2 p0 = unpack2(accp[eloc][0]);
                float2 p1 = unpack2(accp[eloc][1]);
                float2 p2 = unpack2(accp[eloc][2]);
                float2 p3 = unpack2(accp[eloc][3]);
                float x0 = p0.x * pa.x;
                float x1 = p0.y * pa.y;
                float x2 = p1.x * pa.z;
                float x3 = p1.y * pa.w;
                float x4 = p2.x * pb.x;
                float x5 = p2.y * pb.y;
                float x6 = p3.x * pb.z;
                float x7 = p3.y * pb.w;

                float v0 = vw.x, v1 = vw.y, v2 = vw.z;

                float u1x = uvb[le * 9 + 0], u1y = uvb[le * 9 + 1],
                      u1z = uvb[le * 9 + 2];
                float u2x = uvb[le * 9 + 3], u2y = uvb[le * 9 + 4],
                      u2z = uvb[le * 9 + 5];
                float u3x = uvb[le * 9 + 6], u3y = uvb[le * 9 + 7],
                      u3z = uvb[le * 9 + 8];

                // cross(vj,u) = (v1*uz - v2*uy, v2*ux - v0*uz, v0*uy - v1*ux)
                float xv0 = v0 * x1 + x2 * u1x + x3 * u2x + x4 * u3x +
                            x5 * (v1 * u1z - v2 * u1y) +
                            x6 * (v1 * u2z - v2 * u2y) +
                            x7 * (v1 * u3z - v2 * u3y);
                float xv1 = v1 * x1 + x2 * u1y + x3 * u2y + x4 * u3y +
                            x5 * (v2 * u1x - v0 * u1z) +
                            x6 * (v2 * u2x - v0 * u2z) +
                            x7 * (v2 * u3x - v0 * u3z);
                float xv2 = v2 * x1 + x2 * u1z + x3 * u2z + x4 * u3z +
                            x5 * (v0 * u1y - v1 * u1x) +
                            x6 * (v0 * u2y - v1 * u2x) +
                            x7 * (v0 * u3y - v1 * u3x);

                red_add_v4(g_scr + ((size_t)i * FDIM + ff) * 4, x0, xv0, xv1, xv2);
            }
        }
        cur ^= 1;
    }
}

// ---------------- host ----------------
extern "C" void kernel_launch(void* const* d_in, const int* in_sizes, int n_in,
                              void* d_out, int out_size) {
    const float* s = (const float*)d_in[0];
    const float* v = (const float*)d_in[1];
    const float* re1 = (const float*)d_in[2];
    const float* re2 = (const float*)d_in[3];
    const float* re3 = (const float*)d_in[4];
    const float* fc1 = (const float*)d_in[5];
    const float* fc2 = (const float*)d_in[6];
    const float* fc3 = (const float*)d_in[7];
    const float* uv1 = (const float*)d_in[8];
    const float* uv2 = (const float*)d_in[9];
    const float* uv3 = (const float*)d_in[10];
    const int* eidx = (const int*)d_in[11];
    const float* W1 = (const float*)d_in[12];
    const float* b1 = (const float*)d_in[13];
    const float* W2 = (const float*)d_in[14];
    const float* b2 = (const float*)d_in[15];
    const float* Wr = (const float*)d_in[16];
    const float* br = (const float*)d_in[17];
    float* out = (float*)d_out;

    float *hptr, *phiptr;
    cudaGetSymbolAddress((void**)&hptr, g_h);
    cudaGetSymbolAddress((void**)&phiptr, g_phi);

    init_out_kernel<<<256, 256>>>(s, v, out);
    prep_kernel<<<256, 256>>>(v);

    dim3 g1(FDIM / 64, (N_NODES + 127) / 128);
    sgemm_kernel<true, false><<<g1, 256>>>(s, W1, b1, hptr, N_NODES, FDIM, FDIM);

    dim3 g2(PHI_DIM / 64, (N_NODES + 127) / 128);
    sgemm_kernel<false, true><<<g2, 256>>>(hptr, W2, b2, phiptr, N_NODES,
                                           PHI_DIM, FDIM);

    int smem_bytes = (NRBD * FDIM * 2 + 2 * 256) * (int)sizeof(float4) +
                     (2 * 288 + 2 * 32) * (int)sizeof(float) +
                     2 * 2 * 32 * (int)sizeof(int);
    cudaFuncSetAttribute(edge_kernel,
                         cudaFuncAttributeMaxDynamicSharedMemorySize, smem_bytes);
    edge_kernel<<<148, 512, smem_bytes>>>(re1, re2, re3, fc1, fc2, fc3, uv1,
                                          uv2, uv3, eidx, Wr, br);

    merge_kernel<<<256, 256>>>(out);
}

// round 14
// speedup vs baseline: 1.1551x; 1.1551x over previous
#include <cuda_runtime.h>
#include <math.h>
#include <cstdint>

#define N_NODES 10000
#define N_EDGES 160000
#define FDIM 128
#define NRBD 32
#define PHI_DIM 1024

// scratch (static device globals: allocation-free)
__device__ float g_h[N_NODES * FDIM];       // silu(s@W1+b1)
__device__ float g_phi[N_NODES * PHI_DIM];  // phi
__device__ int g_cnt[N_NODES];              // histogram -> cursor
__device__ int g_perm[N_EDGES];             // edge ids sorted by dst

// ---------------- packed f32x2 helpers (Blackwell FFMA2) ----------------
__device__ __forceinline__ unsigned long long pack2(float lo, float hi) {
    unsigned long long r;
    asm("mov.b64 %0, {%1, %2};" : "=l"(r) : "f"(lo), "f"(hi));
    return r;
}
__device__ __forceinline__ unsigned long long fma2(unsigned long long a,
                                                   unsigned long long b,
                                                   unsigned long long c) {
    unsigned long long d;
    asm("fma.rn.f32x2 %0, %1, %2, %3;" : "=l"(d) : "l"(a), "l"(b), "l"(c));
    return d;
}
__device__ __forceinline__ float2 unpack2(unsigned long long p) {
    float2 f;
    asm("mov.b64 {%0, %1}, %2;" : "=f"(f.x), "=f"(f.y) : "l"(p));
    return f;
}

// ---------------- init: out = concat(s, v); zero histogram ----------------
__global__ void init_out_kernel(const float* __restrict__ s,
                                const float* __restrict__ v,
                                float* __restrict__ out) {
    int ns4 = (N_NODES * FDIM) / 4;
    int nv4 = (N_NODES * 3 * FDIM) / 4;
    int total4 = ns4 + nv4;
    for (int t = blockIdx.x * blockDim.x + threadIdx.x; t < total4;
         t += gridDim.x * blockDim.x) {
        float4 val = (t < ns4) ? ((const float4*)s)[t]
                               : ((const float4*)v)[t - ns4];
        ((float4*)out)[t] = val;
    }
    for (int t = blockIdx.x * blockDim.x + threadIdx.x; t < N_NODES;
         t += gridDim.x * blockDim.x)
        g_cnt[t] = 0;
}

// ---------------- sort-by-destination machinery ----------------
__global__ void hist_kernel(const int* __restrict__ eidx) {
    for (int e = blockIdx.x * blockDim.x + threadIdx.x; e < N_EDGES;
         e += gridDim.x * blockDim.x)
        atomicAdd(&g_cnt[eidx[e]], 1);
}

// single block, 1024 threads: exclusive scan of g_cnt -> cursors in g_cnt
__global__ __launch_bounds__(1024) void scan_kernel() {
    __shared__ int part[1024];
    int t = threadIdx.x;
    const int STRIP = (N_NODES + 1023) / 1024;  // 10
    int loc[10];
    int s = 0;
    int base = t * STRIP;
#pragma unroll
    for (int k = 0; k < STRIP; k++) {
        int n = base + k;
        loc[k] = (n < N_NODES) ? g_cnt[n] : 0;
        s += loc[k];
    }
    part[t] = s;
    __syncthreads();
    for (int off = 1; off < 1024; off <<= 1) {
        int v = 0;
        if (t >= off) v = part[t - off];
        __syncthreads();
        if (t >= off) part[t] += v;
        __syncthreads();
    }
    int run = part[t] - s;  // exclusive prefix
#pragma unroll
    for (int k = 0; k < STRIP; k++) {
        int n = base + k;
        if (n < N_NODES) {
            g_cnt[n] = run;
            run += loc[k];
        }
    }
}

__global__ void scatter_kernel(const int* __restrict__ eidx) {
    for (int e = blockIdx.x * blockDim.x + threadIdx.x; e < N_EDGES;
         e += gridDim.x * blockDim.x) {
        int pos = atomicAdd(&g_cnt[eidx[e]], 1);
        g_perm[pos] = e;
    }
}

// ---------------- SGEMM: C = A[M,K] @ B[K,N] + bias, optional SiLU ----------
// BM=128, BN=64, BK=16, TM=8, TN=4, 256 threads, FFMA2 inner loop.
template <bool SILU>
__global__ __launch_bounds__(256) void sgemm_kernel(
    const float* __restrict__ A, const float* __restrict__ B,
    const float* __restrict__ bias, float* __restrict__ C,
    int M, int N, int K) {
    __shared__ float As[16][132];
    __shared__ float Bs[16][64];

    int tid = threadIdx.x;
    int tx = tid % 16, ty = tid / 16;
    int bRow = blockIdx.y * 128, bCol = blockIdx.x * 64;
    int bRowL = tid / 16, bColL = (tid % 16) * 4;

    unsigned long long accp[8][2];
#pragma unroll
    for (int i = 0; i < 8; i++) {
        accp[i][0] = 0ULL;
        accp[i][1] = 0ULL;
    }

    for (int kt = 0; kt < K; kt += 16) {
#pragma unroll
        for (int l = 0; l < 2; l++) {
            int idx = tid + l * 256;
            int row = idx >> 2, c4 = (idx & 3) * 4;
            float4 a = make_float4(0.f, 0.f, 0.f, 0.f);
            int gRow = bRow + row;
            if (gRow < M) a = *(const float4*)(A + (size_t)gRow * K + kt + c4);
            As[c4 + 0][row] = a.x;
            As[c4 + 1][row] = a.y;
            As[c4 + 2][row] = a.z;
            As[c4 + 3][row] = a.w;
        }
        float4 b = *(const float4*)(B + (size_t)(kt + bRowL) * N + bCol + bColL);
        *(float4*)&Bs[bRowL][bColL] = b;
        __syncthreads();

#pragma unroll
        for (int k = 0; k < 16; ++k) {
            float4 bn = *(float4*)&Bs[k][tx * 4];
            unsigned long long pb0 = pack2(bn.x, bn.y);
            unsigned long long pb1 = pack2(bn.z, bn.w);
#pragma unroll
            for (int i = 0; i < 8; i++) {
                float rm = As[k][ty * 8 + i];
                unsigned long long rd = pack2(rm, rm);
                accp[i][0] = fma2(rd, pb0, accp[i][0]);
                accp[i][1] = fma2(rd, pb1, accp[i][1]);
            }
        }
        __syncthreads();
    }

#pragma unroll
    for (int i = 0; i < 8; i++) {
        int r = bRow + ty * 8 + i;
        if (r >= M) continue;
        float2 p0 = unpack2(accp[i][0]);
        float2 p1 = unpack2(accp[i][1]);
        float vals[4] = {p0.x, p0.y, p1.x, p1.y};
#pragma unroll
        for (int j = 0; j < 4; j++) {
            int c = bCol + tx * 4 + j;
            float val = vals[j] + bias[c];
            if (SILU) val = val / (1.0f + expf(-val));
            C[(size_t)r * N + c] = val;
        }
    }
}

// ---------------- fused edge kernel (pipelined, dst-sorted, run-accum) -----
// 512 threads = 4 eslots x 128 features; 8 edges/eslot per 32-edge tile.
// Tiles walk edges in destination-sorted order (g_perm); the epilogue
// accumulates while consecutive edges share a destination and atomically
// flushes only on change (avg degree 16 -> ~4-6x fewer atomic lanes).
__global__ __launch_bounds__(512, 1) void edge_kernel(
    const float* __restrict__ re1, const float* __restrict__ re2,
    const float* __restrict__ re3, const float* __restrict__ fc1,
    const float* __restrict__ fc2, const float* __restrict__ fc3,
    const float* __restrict__ uv1, const float* __restrict__ uv2,
    const float* __restrict__ uv3, const int* __restrict__ eidx,
    const float* __restrict__ Wr, const float* __restrict__ br,
    const float* __restrict__ v, float* __restrict__ out) {
    extern __shared__ float smem[];
    float4* wrA = (float4*)smem;          // [32*128] chunks 0..3
    float4* wrB = wrA + NRBD * FDIM;      // [32*128] chunks 4..7
    float4* rc4 = wrB + NRBD * FDIM;      // [2][32 edges][8]
    float* uvs = (float*)(rc4 + 2 * 256); // [2][32*9]
    float* fcs = uvs + 2 * 288;           // [2][32]
    int* iis = (int*)(fcs + 2 * 32);      // [2][32]
    int* jjs = iis + 2 * 32;              // [2][32]

    int tid = threadIdx.x;

    // one-time Wr load into transposed/split SMEM layout
    for (int idx = tid; idx < NRBD * PHI_DIM; idx += 512) {
        int k = idx >> 10;
        int col = idx & 1023;
        int c = col >> 7, ffi = col & 127;
        float val = Wr[idx];
        float* dst = (c < 4) ? (float*)&wrA[k * FDIM + ffi]
                             : (float*)&wrB[k * FDIM + ffi];
        dst[c & 3] = val;
    }

    int ff = tid & 127;
    int eslot = tid >> 7;

    float brc[8];
#pragma unroll
    for (int c = 0; c < 8; c++) brc[c] = br[c * FDIM + ff];

    float* out_s = out;
    float* out_v = out + (size_t)N_NODES * FDIM;

    const int numTiles = N_EDGES / 32;

    // ---- staging lambda (writes one buffer, no sync) ----
    auto stage = [&](int buf, int tileId) {
        int eBase = tileId * 32;
        if (tid < 256) {
            int t = tid;
            int e = t >> 3;
            int ge = g_perm[eBase + e];
            float c1 = fc1[ge], c2 = fc2[ge], c3 = fc3[ge];
            float4 a = ((const float4*)re1)[ge * 8 + (t & 7)];
            float4 b = ((const float4*)re2)[ge * 8 + (t & 7)];
            float4 c = ((const float4*)re3)[ge * 8 + (t & 7)];
            float4 r;
            r.x = a.x * c1 + b.x * c2 + c.x * c3;
            r.y = a.y * c1 + b.y * c2 + c.y * c3;
            r.z = a.z * c1 + b.z * c2 + c.z * c3;
            r.w = a.w * c1 + b.w * c2 + c.w * c3;
            rc4[buf * 256 + t] = r;
        } else if (tid < 288) {
            int le = tid - 256;
            int ge = g_perm[eBase + le];
            iis[buf * 32 + le] = eidx[ge];
            jjs[buf * 32 + le] = eidx[N_EDGES + ge];
            fcs[buf * 32 + le] = fc1[ge] + fc2[ge] + fc3[ge];
#pragma unroll
            for (int d = 0; d < 3; d++) {
                uvs[buf * 288 + le * 9 + d] = uv1[ge * 3 + d];
                uvs[buf * 288 + le * 9 + 3 + d] = uv2[ge * 3 + d];
                uvs[buf * 288 + le * 9 + 6 + d] = uv3[ge * 3 + d];
            }
        }
    };

    // prologue: stage first tile into buffer 0
    stage(0, blockIdx.x);
    int cur = 0;

    for (int tile = blockIdx.x; tile < numTiles; tile += gridDim.x) {
        __syncthreads();  // staging of buffer `cur` complete; prev reads done

        int nxt = tile + gridDim.x;
        if (nxt < numTiles) stage(1 - cur, nxt);

        const float4* rcb = rc4 + cur * 256;
        const float* fcb = fcs + cur * 32;
        const float* uvb = uvs + cur * 288;
        const int* iib = iis + cur * 32;
        const int* jjb = jjs + cur * 32;

        // W accumulators: 8 edges x 4 chunk-pairs, packed f32x2
        unsigned long long accp[8][4];
#pragma unroll
        for (int e = 0; e < 8; e++) {
            float fs = fcb[eslot * 8 + e];
            accp[e][0] = pack2(fs * brc[0], fs * brc[1]);
            accp[e][1] = pack2(fs * brc[2], fs * brc[3]);
            accp[e][2] = pack2(fs * brc[4], fs * brc[5]);
            accp[e][3] = pack2(fs * brc[6], fs * brc[7]);
        }

#pragma unroll
        for (int kk = 0; kk < 8; ++kk) {
            float4 r[8];
#pragma unroll
            for (int e = 0; e < 8; e++) r[e] = rcb[(eslot * 8 + e) * 8 + kk];
#pragma unroll
            for (int d = 0; d < 4; ++d) {
                int k = kk * 4 + d;
                ulonglong2 wa = *(const ulonglong2*)&wrA[k * FDIM + ff];
                ulonglong2 wb = *(const ulonglong2*)&wrB[k * FDIM + ff];
#pragma unroll
                for (int e = 0; e < 8; e++) {
                    float rv = (d == 0) ? r[e].x
                             : (d == 1) ? r[e].y
                             : (d == 2) ? r[e].z
                                        : r[e].w;
                    unsigned long long rp = pack2(rv, rv);
                    accp[e][0] = fma2(rp, wa.x, accp[e][0]);
                    accp[e][1] = fma2(rp, wa.y, accp[e][1]);
                    accp[e][2] = fma2(rp, wb.x, accp[e][2]);
                    accp[e][3] = fma2(rp, wb.y, accp[e][3]);
                }
            }
        }

        // epilogue: pairs of edges, loads hoisted; run-accumulate by dst i
        int curI = -1;
        float as = 0.f, av0 = 0.f, av1 = 0.f, av2 = 0.f;
#pragma unroll
        for (int pp = 0; pp < 4; pp++) {
            int le0 = eslot * 8 + 2 * pp;
            int le1 = le0 + 1;
            int i0 = iib[le0], j0 = jjb[le0];
            int i1 = iib[le1], j1 = jjb[le1];

            const float* pj0 = g_phi + (size_t)j0 * PHI_DIM + ff;
            const float* pj1 = g_phi + (size_t)j1 * PHI_DIM + ff;
            const float* vj0 = v + (size_t)j0 * (3 * FDIM) + ff;
            const float* vj1 = v + (size_t)j1 * (3 * FDIM) + ff;

            float ph0[8], ph1[8];
#pragma unroll
            for (int c = 0; c < 8; c++) ph0[c] = __ldg(pj0 + c * FDIM);
#pragma unroll
            for (int c = 0; c < 8; c++) ph1[c] = __ldg(pj1 + c * FDIM);
            float va0 = __ldg(vj0), vb0 = __ldg(vj0 + 128), vc0 = __ldg(vj0 + 256);
            float va1 = __ldg(vj1), vb1 = __ldg(vj1 + 128), vc1 = __ldg(vj1 + 256);

#pragma unroll
            for (int q = 0; q < 2; q++) {
                int le = q ? le1 : le0;
                int i = q ? i1 : i0;
                const float* ph = q ? ph1 : ph0;
                float v0 = q ? va1 : va0;
                float v1 = q ? vb1 : vb0;
                float v2 = q ? vc1 : vc0;
                int eloc = le - eslot * 8;
                float2 p0 = unpack2(accp[eloc][0]);
                float2 p1 = unpack2(accp[eloc][1]);
                float2 p2 = unpack2(accp[eloc][2]);
                float2 p3 = unpack2(accp[eloc][3]);
                float x0 = p0.x * ph[0];
                float x1 = p0.y * ph[1];
                float x2 = p1.x * ph[2];
                float x3 = p1.y * ph[3];
                float x4 = p2.x * ph[4];
                float x5 = p2.y * ph[5];
                float x6 = p3.x * ph[6];
                float x7 = p3.y * ph[7];

                float u1x = uvb[le * 9 + 0], u1y = uvb[le * 9 + 1],
                      u1z = uvb[le * 9 + 2];
                float u2x = uvb[le * 9 + 3], u2y = uvb[le * 9 + 4],
                      u2z = uvb[le * 9 + 5];
                float u3x = uvb[le * 9 + 6], u3y = uvb[le * 9 + 7],
                      u3z = uvb[le * 9 + 8];

                // cross(vj,u) = (v1*uz - v2*uy, v2*ux - v0*uz, v0*uy - v1*ux)
                float xv0 = v0 * x1 + x2 * u1x + x3 * u2x + x4 * u3x +
                            x5 * (v1 * u1z - v2 * u1y) +
                            x6 * (v1 * u2z - v2 * u2y) +
                            x7 * (v1 * u3z - v2 * u3y);
                float xv1 = v1 * x1 + x2 * u1y + x3 * u2y + x4 * u3y +
                            x5 * (v2 * u1x - v0 * u1z) +
                            x6 * (v2 * u2x - v0 * u2z) +
                            x7 * (v2 * u3x - v0 * u3z);
                float xv2 = v2 * x1 + x2 * u1z + x3 * u2z + x4 * u3z +
                            x5 * (v0 * u1y - v1 * u1x) +
                            x6 * (v0 * u2y - v1 * u2x) +
                            x7 * (v0 * u3y - v1 * u3x);

                if (i != curI) {
                    if (curI >= 0) {
                        atomicAdd(out_s + (size_t)curI * FDIM + ff, as);
                        float* ov = out_v + (size_t)curI * (3 * FDIM) + ff;
                        atomicAdd(ov, av0);
                        atomicAdd(ov + 128, av1);
                        atomicAdd(ov + 256, av2);
                    }
                    curI = i;
                    as = x0;
                    av0 = xv0;
                    av1 = xv1;
                    av2 = xv2;
                } else {
                    as += x0;
                    av0 += xv0;
                    av1 += xv1;
                    av2 += xv2;
                }
            }
        }
        // final flush for this tile's 8 edges
        atomicAdd(out_s + (size_t)curI * FDIM + ff, as);
        float* ov = out_v + (size_t)curI * (3 * FDIM) + ff;
        atomicAdd(ov, av0);
        atomicAdd(ov + 128, av1);
        atomicAdd(ov + 256, av2);

        cur ^= 1;
    }
}

// ---------------- host ----------------
extern "C" void kernel_launch(void* const* d_in, const int* in_sizes, int n_in,
                              void* d_out, int out_size) {
    const float* s = (const float*)d_in[0];
    const float* v = (const float*)d_in[1];
    const float* re1 = (const float*)d_in[2];
    const float* re2 = (const float*)d_in[3];
    const float* re3 = (const float*)d_in[4];
    const float* fc1 = (const float*)d_in[5];
    const float* fc2 = (const float*)d_in[6];
    const float* fc3 = (const float*)d_in[7];
    const float* uv1 = (const float*)d_in[8];
    const float* uv2 = (const float*)d_in[9];
    const float* uv3 = (const float*)d_in[10];
    const int* eidx = (const int*)d_in[11];
    const float* W1 = (const float*)d_in[12];
    const float* b1 = (const float*)d_in[13];
    const float* W2 = (const float*)d_in[14];
    const float* b2 = (const float*)d_in[15];
    const float* Wr = (const float*)d_in[16];
    const float* br = (const float*)d_in[17];
    float* out = (float*)d_out;

    float *hptr, *phiptr;
    cudaGetSymbolAddress((void**)&hptr, g_h);
    cudaGetSymbolAddress((void**)&phiptr, g_phi);

    init_out_kernel<<<256, 256>>>(s, v, out);
    hist_kernel<<<160, 256>>>(eidx);
    scan_kernel<<<1, 1024>>>();
    scatter_kernel<<<160, 256>>>(eidx);

    dim3 g1(FDIM / 64, (N_NODES + 127) / 128);
    sgemm_kernel<true><<<g1, 256>>>(s, W1, b1, hptr, N_NODES, FDIM, FDIM);

    dim3 g2(PHI_DIM / 64, (N_NODES + 127) / 128);
    sgemm_kernel<false><<<g2, 256>>>(hptr, W2, b2, phiptr, N_NODES, PHI_DIM, FDIM);

    int smem_bytes = (NRBD * FDIM * 2 + 2 * 256) * (int)sizeof(float4) +
                     (2 * 288 + 2 * 32) * (int)sizeof(float) +
                     2 * 2 * 32 * (int)sizeof(int);
    cudaFuncSetAttribute(edge_kernel,
                         cudaFuncAttributeMaxDynamicSharedMemorySize, smem_bytes);
    edge_kernel<<<148, 512, smem_bytes>>>(re1, re2, re3, fc1, fc2, fc3, uv1,
                                          uv2, uv3, eidx, Wr, br, v, out);
}

// round 17
// speedup vs baseline: 1.1651x; 1.0087x over previous
#include <cuda_runtime.h>
#include <math.h>
#include <cstdint>

#define N_NODES 10000
#define N_EDGES 160000
#define FDIM 128
#define NRBD 32
#define PHI_DIM 1024

// scratch (static device globals: allocation-free)
__device__ float g_h[N_NODES * FDIM];       // silu(s@W1+b1)
__device__ float g_phi[N_NODES * PHI_DIM];  // phi

// ---------------- packed f32x2 helpers (Blackwell FFMA2) ----------------
__device__ __forceinline__ unsigned long long pack2(float lo, float hi) {
    unsigned long long r;
    asm("mov.b64 %0, {%1, %2};" : "=l"(r) : "f"(lo), "f"(hi));
    return r;
}
__device__ __forceinline__ unsigned long long fma2(unsigned long long a,
                                                   unsigned long long b,
                                                   unsigned long long c) {
    unsigned long long d;
    asm("fma.rn.f32x2 %0, %1, %2, %3;" : "=l"(d) : "l"(a), "l"(b), "l"(c));
    return d;
}
__device__ __forceinline__ float2 unpack2(unsigned long long p) {
    float2 f;
    asm("mov.b64 {%0, %1}, %2;" : "=f"(f.x), "=f"(f.y) : "l"(p));
    return f;
}

// ---------------- cp.async helpers (sm_80+ plain feature) ----------------
__device__ __forceinline__ void cp_async16(uint32_t dst, const void* src,
                                           int src_sz) {
    asm volatile("cp.async.ca.shared.global [%0], [%1], 16, %2;"
                 :: "r"(dst), "l"(src), "r"(src_sz) : "memory");
}
__device__ __forceinline__ void cp_commit() {
    asm volatile("cp.async.commit_group;" ::: "memory");
}
template <int N>
__device__ __forceinline__ void cp_wait() {
    asm volatile("cp.async.wait_group %0;" :: "n"(N) : "memory");
}

// ---------------- init: out = concat(s, v) ----------------
__global__ void init_out_kernel(const float* __restrict__ s,
                                const float* __restrict__ v,
                                float* __restrict__ out) {
    int ns4 = (N_NODES * FDIM) / 4;
    int nv4 = (N_NODES * 3 * FDIM) / 4;
    int total4 = ns4 + nv4;
    for (int t = blockIdx.x * blockDim.x + threadIdx.x; t < total4;
         t += gridDim.x * blockDim.x) {
        float4 val = (t < ns4) ? ((const float4*)s)[t]
                               : ((const float4*)v)[t - ns4];
        ((float4*)out)[t] = val;
    }
}

// ---------------- SGEMM: C = A[M,K] @ B[K,N] + bias, optional SiLU ----------
// BM=128, BN=64, BK=16, TM=8, TN=4, 256 threads, FFMA2 inner loop,
// cp.async double-buffered tiles.
template <bool SILU>
__global__ __launch_bounds__(256) void sgemm_kernel(
    const float* __restrict__ A, const float* __restrict__ B,
    const float* __restrict__ bias, float* __restrict__ C,
    int M, int N, int K) {
    __shared__ __align__(16) float As[2][128][20];  // row-major, 80B rows
    __shared__ __align__(16) float Bs[2][16][64];

    int tid = threadIdx.x;
    int tx = tid % 16, ty = tid / 16;
    int bRow = blockIdx.y * 128, bCol = blockIdx.x * 64;
    int bRowL = tid / 16, bColL = (tid % 16) * 4;

    auto loadTiles = [&](int buf, int kt) {
        // A tile: 128 rows x 16 cols = 512 x 16B segments; 2 per thread
#pragma unroll
        for (int l = 0; l < 2; l++) {
            int idx = tid + l * 256;
            int row = idx >> 2, seg = idx & 3;
            int gRow = bRow + row;
            const float* src = A + (size_t)gRow * K + kt + seg * 4;
            uint32_t dst = (uint32_t)__cvta_generic_to_shared(
                &As[buf][row][seg * 4]);
            cp_async16(dst, src, (gRow < M) ? 16 : 0);
        }
        // B tile: 16 x 64 = 256 x 16B segments; 1 per thread
        const float* srcB = B + (size_t)(kt + bRowL) * N + bCol + bColL;
        uint32_t dstB = (uint32_t)__cvta_generic_to_shared(&Bs[buf][bRowL][bColL]);
        cp_async16(dstB, srcB, 16);
    };

    unsigned long long accp[8][2];
#pragma unroll
    for (int i = 0; i < 8; i++) {
        accp[i][0] = 0ULL;
        accp[i][1] = 0ULL;
    }

    const int NT = K / 16;
    loadTiles(0, 0);
    cp_commit();

    int buf = 0;
    for (int it = 0; it < NT; ++it) {
        if (it + 1 < NT) {
            loadTiles(buf ^ 1, (it + 1) * 16);
            cp_commit();
            cp_wait<1>();
        } else {
            cp_wait<0>();
        }
        __syncthreads();

#pragma unroll
        for (int k = 0; k < 16; ++k) {
            float4 bn = *(float4*)&Bs[buf][k][tx * 4];
            unsigned long long pb0 = pack2(bn.x, bn.y);
            unsigned long long pb1 = pack2(bn.z, bn.w);
#pragma unroll
            for (int i = 0; i < 8; i++) {
                float rm = As[buf][ty * 8 + i][k];
                unsigned long long rd = pack2(rm, rm);
                accp[i][0] = fma2(rd, pb0, accp[i][0]);
                accp[i][1] = fma2(rd, pb1, accp[i][1]);
            }
        }
        __syncthreads();  // readers done before this buf is refilled
        buf ^= 1;
    }

#pragma unroll
    for (int i = 0; i < 8; i++) {
        int r = bRow + ty * 8 + i;
        if (r >= M) continue;
        float2 p0 = unpack2(accp[i][0]);
        float2 p1 = unpack2(accp[i][1]);
        float vals[4] = {p0.x, p0.y, p1.x, p1.y};
#pragma unroll
        for (int j = 0; j < 4; j++) {
            int c = bCol + tx * 4 + j;
            float val = vals[j] + bias[c];
            if (SILU) val = val / (1.0f + expf(-val));
            C[(size_t)r * N + c] = val;
        }
    }
}

// ---------------- fused edge kernel: 4 independent warpgroups --------------
// 512 threads = 4 groups x 128 ff-threads. Each group owns an independent
// 8-edge tile stream with its own double-buffered rcomb/meta and a NAMED
// barrier (group scope) -- no CTA-wide sync in the loop, so epilogue
// stragglers stall only 4 warps and groups drift to smooth LSU bursts.
// Wr is CTA-shared read-only (one __syncthreads after init).
__global__ __launch_bounds__(512, 1) void edge_kernel(
    const float* __restrict__ re1, const float* __restrict__ re2,
    const float* __restrict__ re3, const float* __restrict__ fc1,
    const float* __restrict__ fc2, const float* __restrict__ fc3,
    const float* __restrict__ uv1, const float* __restrict__ uv2,
    const float* __restrict__ uv3, const int* __restrict__ eidx,
    const float* __restrict__ Wr, const float* __restrict__ br,
    const float* __restrict__ v, float* __restrict__ out) {
    extern __shared__ float smem[];
    float4* wrA = (float4*)smem;            // [32*128] chunks 0..3
    float4* wrB = wrA + NRBD * FDIM;        // [32*128] chunks 4..7
    float4* rcAll = wrB + NRBD * FDIM;      // [4 g][2 buf][8 e][8] float4
    float* uvsAll = (float*)(rcAll + 4 * 2 * 64);  // [4][2][8*9]
    float* fcsAll = uvsAll + 4 * 2 * 72;           // [4][2][8]
    int* iisAll = (int*)(fcsAll + 4 * 2 * 8);      // [4][2][8]
    int* jjsAll = iisAll + 4 * 2 * 8;              // [4][2][8]

    int tid = threadIdx.x;
    int g = tid >> 7;      // group 0..3 (warps g*4..g*4+3)
    int ff = tid & 127;    // feature lane within group
    int ltid = ff;

    // one-time Wr load into transposed/split SMEM layout (whole CTA)
    for (int idx = tid; idx < NRBD * PHI_DIM; idx += 512) {
        int k = idx >> 10;
        int col = idx & 1023;
        int c = col >> 7, ffi = col & 127;
        float val = Wr[idx];
        float* dst = (c < 4) ? (float*)&wrA[k * FDIM + ffi]
                             : (float*)&wrB[k * FDIM + ffi];
        dst[c & 3] = val;
    }

    float4* rcg = rcAll + g * (2 * 64);
    float* uvg = uvsAll + g * (2 * 72);
    float* fcg = fcsAll + g * (2 * 8);
    int* iig = iisAll + g * (2 * 8);
    int* jjg = jjsAll + g * (2 * 8);

    float brc[8];
#pragma unroll
    for (int c = 0; c < 8; c++) brc[c] = br[c * FDIM + ff];

    float* out_s = out;
    float* out_v = out + (size_t)N_NODES * FDIM;

    const int numT = N_EDGES / 8;                 // 8-edge tiles: 20000
    const int G = blockIdx.x * 4 + g;             // global group id
    const int nG = gridDim.x * 4;                 // 592 streams

    // ---- group staging (no sync inside) ----
    auto stage = [&](int buf, int tileId) {
        int eBase = tileId * 8;
        if (ltid < 64) {
            int e = ltid >> 3, kq = ltid & 7;
            int ge = eBase + e;
            float c1 = fc1[ge], c2 = fc2[ge], c3 = fc3[ge];
            float4 a = ((const float4*)re1)[ge * 8 + kq];
            float4 b = ((const float4*)re2)[ge * 8 + kq];
            float4 c = ((const float4*)re3)[ge * 8 + kq];
            float4 r;
            r.x = a.x * c1 + b.x * c2 + c.x * c3;
            r.y = a.y * c1 + b.y * c2 + c.y * c3;
            r.z = a.z * c1 + b.z * c2 + c.z * c3;
            r.w = a.w * c1 + b.w * c2 + c.w * c3;
            rcg[buf * 64 + e * 8 + kq] = r;
        } else if (ltid < 72) {
            int le = ltid - 64;
            int ge = eBase + le;
            iig[buf * 8 + le] = eidx[ge];
            jjg[buf * 8 + le] = eidx[N_EDGES + ge];
            fcg[buf * 8 + le] = fc1[ge] + fc2[ge] + fc3[ge];
#pragma unroll
            for (int d = 0; d < 3; d++) {
                uvg[buf * 72 + le * 9 + d] = uv1[ge * 3 + d];
                uvg[buf * 72 + le * 9 + 3 + d] = uv2[ge * 3 + d];
                uvg[buf * 72 + le * 9 + 6 + d] = uv3[ge * 3 + d];
            }
        }
    };

    // group-scope named barrier (ids 1..4; 0 is __syncthreads)
    int barId = g + 1;
    auto barG = [&] {
        asm volatile("bar.sync %0, 128;" :: "r"(barId) : "memory");
    };

    // prologue: stage first tile; one CTA sync covers Wr + initial staging
    stage(0, G);
    __syncthreads();

    int cur = 0;
    for (int tile = G; tile < numT; tile += nG) {
        barG();  // staging of `cur` complete; group's prior reads done

        int nxt = tile + nG;
        if (nxt < numT) stage(1 - cur, nxt);

        const float4* rcb = rcg + cur * 64;
        const float* fcb = fcg + cur * 8;
        const float* uvb = uvg + cur * 72;
        const int* iib = iig + cur * 8;
        const int* jjb = jjg + cur * 8;

        // W accumulators: 8 edges x 4 chunk-pairs, packed f32x2
        unsigned long long accp[8][4];
#pragma unroll
        for (int e = 0; e < 8; e++) {
            float fs = fcb[e];
            accp[e][0] = pack2(fs * brc[0], fs * brc[1]);
            accp[e][1] = pack2(fs * brc[2], fs * brc[3]);
            accp[e][2] = pack2(fs * brc[4], fs * brc[5]);
            accp[e][3] = pack2(fs * brc[6], fs * brc[7]);
        }

#pragma unroll
        for (int kk = 0; kk < 8; ++kk) {
            float4 r[8];
#pragma unroll
            for (int e = 0; e < 8; e++) r[e] = rcb[e * 8 + kk];
#pragma unroll
            for (int d = 0; d < 4; ++d) {
                int k = kk * 4 + d;
                ulonglong2 wa = *(const ulonglong2*)&wrA[k * FDIM + ff];
                ulonglong2 wb = *(const ulonglong2*)&wrB[k * FDIM + ff];
#pragma unroll
                for (int e = 0; e < 8; e++) {
                    float rv = (d == 0) ? r[e].x
                             : (d == 1) ? r[e].y
                             : (d == 2) ? r[e].z
                                        : r[e].w;
                    unsigned long long rp = pack2(rv, rv);
                    accp[e][0] = fma2(rp, wa.x, accp[e][0]);
                    accp[e][1] = fma2(rp, wa.y, accp[e][1]);
                    accp[e][2] = fma2(rp, wb.x, accp[e][2]);
                    accp[e][3] = fma2(rp, wb.y, accp[e][3]);
                }
            }
        }

        // epilogue: pairs of edges; hoist all global loads before the math
#pragma unroll
        for (int pp = 0; pp < 4; pp++) {
            int le0 = 2 * pp;
            int le1 = le0 + 1;
            int i0 = iib[le0], j0 = jjb[le0];
            int i1 = iib[le1], j1 = jjb[le1];

            const float* pj0 = g_phi + (size_t)j0 * PHI_DIM + ff;
            const float* pj1 = g_phi + (size_t)j1 * PHI_DIM + ff;
            const float* vj0 = v + (size_t)j0 * (3 * FDIM) + ff;
            const float* vj1 = v + (size_t)j1 * (3 * FDIM) + ff;

            float ph0[8], ph1[8];
#pragma unroll
            for (int c = 0; c < 8; c++) ph0[c] = __ldg(pj0 + c * FDIM);
#pragma unroll
            for (int c = 0; c < 8; c++) ph1[c] = __ldg(pj1 + c * FDIM);
            float va0 = __ldg(vj0), vb0 = __ldg(vj0 + 128), vc0 = __ldg(vj0 + 256);
            float va1 = __ldg(vj1), vb1 = __ldg(vj1 + 128), vc1 = __ldg(vj1 + 256);

#pragma unroll
            for (int q = 0; q < 2; q++) {
                int le = q ? le1 : le0;
                int i = q ? i1 : i0;
                const float* ph = q ? ph1 : ph0;
                float v0 = q ? va1 : va0;
                float v1 = q ? vb1 : vb0;
                float v2 = q ? vc1 : vc0;
                float2 p0 = unpack2(accp[le][0]);
                float2 p1 = unpack2(accp[le][1]);
                float2 p2 = unpack2(accp[le][2]);
                float2 p3 = unpack2(accp[le][3]);
                float x0 = p0.x * ph[0];
                float x1 = p0.y * ph[1];
                float x2 = p1.x * ph[2];
                float x3 = p1.y * ph[3];
                float x4 = p2.x * ph[4];
                float x5 = p2.y * ph[5];
                float x6 = p3.x * ph[6];
                float x7 = p3.y * ph[7];

                float u1x = uvb[le * 9 + 0], u1y = uvb[le * 9 + 1],
                      u1z = uvb[le * 9 + 2];
                float u2x = uvb[le * 9 + 3], u2y = uvb[le * 9 + 4],
                      u2z = uvb[le * 9 + 5];
                float u3x = uvb[le * 9 + 6], u3y = uvb[le * 9 + 7],
                      u3z = uvb[le * 9 + 8];

                // cross(vj,u) = (v1*uz - v2*uy, v2*ux - v0*uz, v0*uy - v1*ux)
                float xv0 = v0 * x1 + x2 * u1x + x3 * u2x + x4 * u3x +
                            x5 * (v1 * u1z - v2 * u1y) +
                            x6 * (v1 * u2z - v2 * u2y) +
                            x7 * (v1 * u3z - v2 * u3y);
                float xv1 = v1 * x1 + x2 * u1y + x3 * u2y + x4 * u3y +
                            x5 * (v2 * u1x - v0 * u1z) +
                            x6 * (v2 * u2x - v0 * u2z) +
                            x7 * (v2 * u3x - v0 * u3z);
                float xv2 = v2 * x1 + x2 * u1z + x3 * u2z + x4 * u3z +
                            x5 * (v0 * u1y - v1 * u1x) +
                            x6 * (v0 * u2y - v1 * u2x) +
                            x7 * (v0 * u3y - v1 * u3x);

                atomicAdd(out_s + (size_t)i * FDIM + ff, x0);
                float* ov = out_v + (size_t)i * (3 * FDIM) + ff;
                atomicAdd(ov, xv0);
                atomicAdd(ov + 128, xv1);
                atomicAdd(ov + 256, xv2);
            }
        }
        cur ^= 1;
    }
}

// ---------------- host ----------------
extern "C" void kernel_launch(void* const* d_in, const int* in_sizes, int n_in,
                              void* d_out, int out_size) {
    const float* s = (const float*)d_in[0];
    const float* v = (const float*)d_in[1];
    const float* re1 = (const float*)d_in[2];
    const float* re2 = (const float*)d_in[3];
    const float* re3 = (const float*)d_in[4];
    const float* fc1 = (const float*)d_in[5];
    const float* fc2 = (const float*)d_in[6];
    const float* fc3 = (const float*)d_in[7];
    const float* uv1 = (const float*)d_in[8];
    const float* uv2 = (const float*)d_in[9];
    const float* uv3 = (const float*)d_in[10];
    const int* eidx = (const int*)d_in[11];
    const float* W1 = (const float*)d_in[12];
    const float* b1 = (const float*)d_in[13];
    const float* W2 = (const float*)d_in[14];
    const float* b2 = (const float*)d_in[15];
    const float* Wr = (const float*)d_in[16];
    const float* br = (const float*)d_in[17];
    float* out = (float*)d_out;

    float *hptr, *phiptr;
    cudaGetSymbolAddress((void**)&hptr, g_h);
    cudaGetSymbolAddress((void**)&phiptr, g_phi);

    init_out_kernel<<<256, 256>>>(s, v, out);

    dim3 g1(FDIM / 64, (N_NODES + 127) / 128);
    sgemm_kernel<true><<<g1, 256>>>(s, W1, b1, hptr, N_NODES, FDIM, FDIM);

    dim3 g2(PHI_DIM / 64, (N_NODES + 127) / 128);
    sgemm_kernel<false><<<g2, 256>>>(hptr, W2, b2, phiptr, N_NODES, PHI_DIM, FDIM);

    int smem_bytes = (NRBD * FDIM * 2 + 4 * 2 * 64) * (int)sizeof(float4) +
                     (4 * 2 * 72 + 4 * 2 * 8) * (int)sizeof(float) +
                     2 * 4 * 2 * 8 * (int)sizeof(int);
    cudaFuncSetAttribute(edge_kernel,
                         cudaFuncAttributeMaxDynamicSharedMemorySize, smem_bytes);
    edge_kernel<<<148, 512, smem_bytes>>>(re1, re2, re3, fc1, fc2, fc3, uv1,
                                          uv2, uv3, eidx, Wr, br, v, out);
}